// round 15
// baseline (speedup 1.0000x reference)
#include <cuda_runtime.h>
#include <cstdint>

#define EPS 1e-5f
#define Nn 8
#define Cc 256
#define Hh 64
#define Ww 64
#define HW 4096
#define OC 64
#define Pp 36

typedef unsigned long long u64;
typedef unsigned int u32;
typedef unsigned short u16;

__device__ __forceinline__ u64 pack2(float x, float y) {
    u64 r; asm("mov.b64 %0, {%1,%2};" : "=l"(r) : "f"(x), "f"(y)); return r;
}
__device__ __forceinline__ void fma2(u64 &d, u64 a, u64 b) {
    asm("fma.rn.f32x2 %0, %1, %2, %0;" : "+l"(d) : "l"(a), "l"(b));
}
__device__ __forceinline__ float2 unpack2(u64 v) {
    float2 r; asm("mov.b64 {%0,%1}, %2;" : "=f"(r.x), "=f"(r.y) : "l"(v)); return r;
}
__device__ __forceinline__ u32 smem_u32(const void* p) {
    u32 a;
    asm("{ .reg .u64 t; cvta.to.shared.u64 t, %1; cvt.u32.u64 %0, t; }" : "=r"(a) : "l"(p));
    return a;
}
__device__ __forceinline__ void ldsm4(u32& r0, u32& r1, u32& r2, u32& r3, u32 addr) {
    asm volatile("ldmatrix.sync.aligned.m8n8.x4.shared.b16 {%0,%1,%2,%3}, [%4];"
                 : "=r"(r0), "=r"(r1), "=r"(r2), "=r"(r3) : "r"(addr));
}
__device__ __forceinline__ void ldsm4t(u32& r0, u32& r1, u32& r2, u32& r3, u32 addr) {
    asm volatile("ldmatrix.sync.aligned.m8n8.x4.trans.shared.b16 {%0,%1,%2,%3}, [%4];"
                 : "=r"(r0), "=r"(r1), "=r"(r2), "=r"(r3) : "r"(addr));
}
__device__ __forceinline__ void mma16816(float* c, u32 a0, u32 a1, u32 a2, u32 a3,
                                          u32 b0, u32 b1) {
    asm volatile("mma.sync.aligned.m16n8k16.row.col.f32.bf16.bf16.f32 "
                 "{%0,%1,%2,%3}, {%4,%5,%6,%7}, {%8,%9}, {%0,%1,%2,%3};"
                 : "+f"(c[0]), "+f"(c[1]), "+f"(c[2]), "+f"(c[3])
                 : "r"(a0), "r"(a1), "r"(a2), "r"(a3), "r"(b0), "r"(b1));
}
__device__ __forceinline__ void split2(float vx, float vy, u32& hi, u32& lo) {
    u32 h; asm("cvt.rn.bf16x2.f32 %0, %1, %2;" : "=r"(h) : "f"(vy), "f"(vx));
    float hx = __uint_as_float(h << 16);
    float hy = __uint_as_float(h & 0xffff0000u);
    u32 l; asm("cvt.rn.bf16x2.f32 %0, %1, %2;" : "=r"(l) : "f"(vy - hy), "f"(vx - hx));
    hi = h; lo = l;
}
__device__ __forceinline__ u16 bf16hi(float v) {
    u16 h; asm("cvt.rn.bf16.f32 %0, %1;" : "=h"(h) : "f"(v)); return h;
}
__device__ __forceinline__ void cp_async16(u32 dst, const void* src, u32 srcsz) {
    asm volatile("cp.async.cg.shared.global [%0], [%1], 16, %2;"
                 :: "r"(dst), "l"(src), "r"(srcsz));
}
__device__ __forceinline__ void cp_commit() { asm volatile("cp.async.commit_group;"); }
__device__ __forceinline__ void cp_wait1() { asm volatile("cp.async.wait_group 1;" ::: "memory"); }
__device__ __forceinline__ void cp_wait0() { asm volatile("cp.async.wait_group 0;" ::: "memory"); }
__device__ __forceinline__ void stcs4(float* p, float4 v) {
    asm volatile("st.global.cs.v4.f32 [%0], {%1,%2,%3,%4};"
                 :: "l"(p), "f"(v.x), "f"(v.y), "f"(v.z), "f"(v.w));
}

// named barriers: 1 = weights group (256), 2 = reassemble group (256),
// 4/5 = producer->consumer handoff for wts buffer 0/1 (512 total)
#define BARW() asm volatile("bar.sync 1, 256;" ::: "memory")
#define BARR() asm volatile("bar.sync 2, 256;" ::: "memory")

// ---------------------------------------------------------------------------
// smem layout (dynamic, 187712 B):
//   [0      , 105280)  weights scratch (phase aliasing identical to R14)
//   [105280 , 125760)  wts buf0 [128 px][40 f32]
//   [125760 , 146240)  wts buf1
//   [146240 , 187712)  halo ring 3 x [8ch][6rows][72f]
// ---------------------------------------------------------------------------
#define S_AHI   0
#define S_ALO   34816
#define S_WHI   69632
#define S_WLO   87040
#define S_CST   104448
#define S2_AHI  0
#define S2_ALO  17408
#define S2_WHI  34816
#define S2_WLO  47872
#define S2_L    60928
#define S_WTS0  105280
#define S_WTS1  125760
#define S_HALO  146240
#define CHUNKB  13824
#define SMEMF   187712

extern "C" __global__ void __launch_bounds__(512, 1)
k_fused(const float* __restrict__ x,
        const float* __restrict__ w0, const float* __restrict__ b0,
        const float* __restrict__ bn0_g, const float* __restrict__ bn0_b,
        const float* __restrict__ bn0_m, const float* __restrict__ bn0_v,
        const float* __restrict__ w1, const float* __restrict__ b1,
        const float* __restrict__ bn1_g, const float* __restrict__ bn1_b,
        const float* __restrict__ bn1_m, const float* __restrict__ bn1_v,
        float* __restrict__ out)
{
    extern __shared__ char smem[];
    const u32 sb = smem_u32(smem);
    const int n   = blockIdx.y;
    const int hr4 = blockIdx.x * 4;      // first of 4 h-rows for this CTA

    if (threadIdx.x < 256) {
        // ===================== WEIGHTS PRODUCER (warps 0-7) =====================
        const int t = threadIdx.x;
        float* cA0 = (float*)(smem + S_CST);
        float* cB0 = cA0 + 64;
        float* cA1 = cB0 + 64;
        float* cB1 = cA1 + 40;
        float* L   = (float*)(smem + S2_L);

        if (t < 64) {
            float A = bn0_g[t] * rsqrtf(bn0_v[t] + EPS);
            cA0[t] = A;
            cB0[t] = (b0[t] - bn0_m[t]) * A + bn0_b[t];
        } else if (t < 64 + 40) {
            int i = t - 64;
            if (i < Pp) {
                float A = bn1_g[i] * rsqrtf(bn1_v[i] + EPS);
                cA1[i] = A;
                cB1[i] = (b1[i] - bn1_m[i]) * A + bn1_b[i];
            } else { cA1[i] = 0.f; cB1[i] = 0.f; }
        }

        float2 w1r[5];
        #pragma unroll
        for (int r = 0; r < 5; r++) {
            int i = t + 256 * r;
            w1r[r] = *(const float2*)(w1 + (i >> 5) * OC + (i & 31) * 2);
        }

        const int warp = t >> 5, lane = t & 31;
        const int mat = lane >> 3, mr = lane & 7;
        const int m0 = warp * 16;
        const int g  = lane >> 2, tq = lane & 3;
        const u32 a_off = (u32)((((mat >> 1) * 8) + mr) * 272 + (m0 + (mat & 1) * 8) * 2);
        const u32 b_off = (u32)((((mat >> 1) * 8) + mr) * 272 + (mat & 1) * 16);

        #pragma unroll 1
        for (int p = 0; p < 2; p++) {
            const int p0 = blockIdx.x * 256 + p * 128;   // flat pixel base (2 rows)
            float acc[8][4];
            #pragma unroll
            for (int i = 0; i < 8; i++)
                #pragma unroll
                for (int j = 0; j < 4; j++) acc[i][j] = 0.f;

            #pragma unroll 1
            for (int h = 0; h < 2; h++) {
                BARW();
                {
                    const float4* xr = (const float4*)(x + ((size_t)n * Cc + h * 128 + warp * 16) * HW + p0);
                    char* ahb = smem + S_AHI + (warp * 16) * 272 + lane * 8;
                    char* alb = smem + S_ALO + (warp * 16) * 272 + lane * 8;
                    #pragma unroll 8
                    for (int rr = 0; rr < 16; rr++) {
                        float4 v = xr[lane];
                        u32 h0, l0, h1, l1;
                        split2(v.x, v.y, h0, l0);
                        split2(v.z, v.w, h1, l1);
                        *(uint2*)(ahb) = make_uint2(h0, h1);
                        *(uint2*)(alb) = make_uint2(l0, l1);
                        xr += HW / 4;
                        ahb += 272; alb += 272;
                    }
                }
                {
                    #pragma unroll 8
                    for (int it = 0; it < 8; it++) {
                        int oc = it * 8 + warp;
                        float4 v = *(const float4*)(w0 + (size_t)oc * Cc + h * 128 + lane * 4);
                        u32 h0, l0, h1, l1;
                        split2(v.x, v.y, h0, l0);
                        split2(v.z, v.w, h1, l1);
                        *(uint2*)(smem + S_WHI + oc * 272 + lane * 8) = make_uint2(h0, h1);
                        *(uint2*)(smem + S_WLO + oc * 272 + lane * 8) = make_uint2(l0, l1);
                    }
                }
                BARW();

                #pragma unroll
                for (int ks = 0; ks < 8; ks++) {
                    u32 ah0, ah1, ah2, ah3, al0, al1, al2, al3;
                    ldsm4t(ah0, ah1, ah2, ah3, sb + S_AHI + ks * 4352 + a_off);
                    ldsm4t(al0, al1, al2, al3, sb + S_ALO + ks * 4352 + a_off);
                    #pragma unroll
                    for (int j = 0; j < 4; j++) {
                        u32 bh0, bh1, bh2, bh3, bl0, bl1, bl2, bl3;
                        ldsm4(bh0, bh1, bh2, bh3, sb + S_WHI + j * 16 * 272 + ks * 32 + b_off);
                        ldsm4(bl0, bl1, bl2, bl3, sb + S_WLO + j * 16 * 272 + ks * 32 + b_off);
                        mma16816(acc[2 * j],     ah0, ah1, ah2, ah3, bh0, bh1);
                        mma16816(acc[2 * j],     al0, al1, al2, al3, bh0, bh1);
                        mma16816(acc[2 * j],     ah0, ah1, ah2, ah3, bl0, bl1);
                        mma16816(acc[2 * j + 1], ah0, ah1, ah2, ah3, bh2, bh3);
                        mma16816(acc[2 * j + 1], al0, al1, al2, al3, bh2, bh3);
                        mma16816(acc[2 * j + 1], ah0, ah1, ah2, ah3, bl2, bl3);
                    }
                }
            }
            BARW();

            // epilogue: BN0 + ReLU -> As2 bf16 hi/lo
            {
                const int pxa = m0 + g, pxb = m0 + g + 8;
                #pragma unroll
                for (int j = 0; j < 8; j++) {
                    int oc0 = 8 * j + 2 * tq, oc1 = oc0 + 1;
                    float Aa = cA0[oc0], Ba = cB0[oc0];
                    float Ab = cA0[oc1], Bb = cB0[oc1];
                    float v00 = fmaxf(fmaf(acc[j][0], Aa, Ba), 0.f);
                    float v01 = fmaxf(fmaf(acc[j][1], Ab, Bb), 0.f);
                    float v10 = fmaxf(fmaf(acc[j][2], Aa, Ba), 0.f);
                    float v11 = fmaxf(fmaf(acc[j][3], Ab, Bb), 0.f);
                    #pragma unroll
                    for (int q = 0; q < 4; q++) {
                        float v  = (q == 0) ? v00 : (q == 1) ? v01 : (q == 2) ? v10 : v11;
                        int oc   = (q & 1) ? oc1 : oc0;
                        int px   = (q & 2) ? pxb : pxa;
                        u16 hi = bf16hi(v);
                        float hf = __uint_as_float(((u32)hi) << 16);
                        u16 lo = bf16hi(v - hf);
                        *(u16*)(smem + S2_AHI + oc * 272 + px * 2) = hi;
                        *(u16*)(smem + S2_ALO + oc * 272 + px * 2) = lo;
                    }
                }
            }
            #pragma unroll
            for (int r = 0; r < 5; r++) {
                int i = t + 256 * r;
                int pr = i >> 5, oq = i & 31;
                u32 hi, lo;
                split2(w1r[r].x, w1r[r].y, hi, lo);
                *(u32*)(smem + S2_WHI + pr * 272 + oq * 4) = hi;
                *(u32*)(smem + S2_WLO + pr * 272 + oq * 4) = lo;
            }
            for (int i = t; i < 8 * 68; i += 256) {
                int rw = 40 + i / 68, col = i % 68;
                *(u32*)(smem + S2_WHI + rw * 272 + col * 4) = 0;
                *(u32*)(smem + S2_WLO + rw * 272 + col * 4) = 0;
            }
            BARW();

            // MMA1: logits [128, 40]
            float d1[5][4];
            #pragma unroll
            for (int i = 0; i < 5; i++)
                #pragma unroll
                for (int j = 0; j < 4; j++) d1[i][j] = 0.f;

            #pragma unroll
            for (int ks = 0; ks < 4; ks++) {
                u32 ah0, ah1, ah2, ah3, al0, al1, al2, al3;
                ldsm4t(ah0, ah1, ah2, ah3, sb + S2_AHI + ks * 4352 + a_off);
                ldsm4t(al0, al1, al2, al3, sb + S2_ALO + ks * 4352 + a_off);
                #pragma unroll
                for (int rb = 0; rb < 3; rb++) {
                    u32 bh0, bh1, bh2, bh3, bl0, bl1, bl2, bl3;
                    ldsm4(bh0, bh1, bh2, bh3, sb + S2_WHI + rb * 4352 + ks * 32 + b_off);
                    ldsm4(bl0, bl1, bl2, bl3, sb + S2_WLO + rb * 4352 + ks * 32 + b_off);
                    int nt = 2 * rb;
                    mma16816(d1[nt], ah0, ah1, ah2, ah3, bh0, bh1);
                    mma16816(d1[nt], al0, al1, al2, al3, bh0, bh1);
                    mma16816(d1[nt], ah0, ah1, ah2, ah3, bl0, bl1);
                    if (rb < 2) {
                        mma16816(d1[nt + 1], ah0, ah1, ah2, ah3, bh2, bh3);
                        mma16816(d1[nt + 1], al0, al1, al2, al3, bh2, bh3);
                        mma16816(d1[nt + 1], ah0, ah1, ah2, ah3, bl2, bl3);
                    }
                }
            }
            #pragma unroll
            for (int nt = 0; nt < 5; nt++) {
                int pc0 = 8 * nt + 2 * tq, pc1 = pc0 + 1;
                float Aa = cA1[pc0], Ba = cB1[pc0];
                float Ab = cA1[pc1], Bb = cB1[pc1];
                L[(m0 + g) * 49 + pc0]     = fmaxf(fmaf(d1[nt][0], Aa, Ba), 0.f);
                L[(m0 + g) * 49 + pc1]     = fmaxf(fmaf(d1[nt][1], Ab, Bb), 0.f);
                L[(m0 + g + 8) * 49 + pc0] = fmaxf(fmaf(d1[nt][2], Aa, Ba), 0.f);
                L[(m0 + g + 8) * 49 + pc1] = fmaxf(fmaf(d1[nt][3], Ab, Bb), 0.f);
            }
            BARW();

            // softmax -> wts buf[p] ([px][40])
            {
                float* wbuf = (float*)(smem + (p ? S_WTS1 : S_WTS0));
                const int px = t & 127;
                const int hh = t >> 7;
                const float* Lp = L + px * 49;
                #pragma unroll
                for (int uu = 0; uu < 2; uu++) {
                    int u = hh + 2 * uu;
                    float e[9], mx = -1e30f;
                    #pragma unroll
                    for (int k = 0; k < 9; k++) { e[k] = Lp[k * 4 + u]; mx = fmaxf(mx, e[k]); }
                    float s = 0.f;
                    #pragma unroll
                    for (int k = 0; k < 9; k++) { float q = __expf(e[k] - mx); e[k] = q; s += q; }
                    float inv = 1.f / s;
                    #pragma unroll
                    for (int k = 0; k < 9; k++) wbuf[px * 40 + k * 4 + u] = e[k] * inv;
                }
            }
            __threadfence_block();
            if (p == 0) asm volatile("bar.arrive 4, 512;" ::: "memory");
            else        asm volatile("bar.arrive 5, 512;" ::: "memory");
        }
    } else {
        // ===================== REASSEMBLE CONSUMER (warps 8-15) =====================
        const int t2   = threadIdx.x - 256;
        const int lane = t2 & 31;
        const int warp2 = t2 >> 5;
        const int row  = warp2 & 1;      // row within 2-row pass
        const int cq   = warp2 >> 1;     // channel quarter within 8-ch chunk (2 ch)
        const float* xb = x + (size_t)n * Cc * HW;

        // hoisted loader: chunk = [8ch][6rows][72f] = 864 vec4; 4 slots/thread
        u32  smOff[4];
        int  gOff[4];
        bool pred[4], act[4];
        #pragma unroll
        for (int i = 0; i < 4; i++) {
            int idx = i * 256 + t2;
            act[i] = idx < 864;
            int ch  = idx / 108;
            int rem = idx - ch * 108;
            int rr  = rem / 18, j = rem - rr * 18;
            bool rok = ((unsigned)(hr4 - 1 + rr) < (unsigned)Hh);
            bool cok = (j >= 1) && (j <= 16);
            pred[i]  = act[i] && rok && cok;
            smOff[i] = (u32)(((ch * 6 + rr) * 72 + 4 * j) * 4);
            gOff[i]  = ch * HW + (hr4 - 1 + rr) * Ww + (4 * j - 4);
        }

        #pragma unroll 1
        for (int p = 0; p < 2; p++) {
            BARR();   // ring slots free from previous pass

            // prefetch chunks 0,1 (overlaps producer compute)
            #pragma unroll
            for (int c = 0; c < 2; c++) {
                const float* gch = xb + (size_t)(c * 8) * HW;
                u32 sb2 = sb + S_HALO + c * CHUNKB;
                #pragma unroll
                for (int i = 0; i < 4; i++)
                    if (act[i]) cp_async16(sb2 + smOff[i], pred[i] ? gch + gOff[i] : xb,
                                           pred[i] ? 16u : 0u);
                cp_commit();
            }

            // wait for wts buffer p
            if (p == 0) asm volatile("bar.sync 4, 512;" ::: "memory");
            else        asm volatile("bar.sync 5, 512;" ::: "memory");

            // weights -> registers, packed across the pixel pair
            u64 wk[9][4];
            {
                const float* wbuf = (const float*)(smem + (p ? S_WTS1 : S_WTS0));
                const int pxl = row * 64 + 2 * lane;
                #pragma unroll
                for (int k = 0; k < 9; k++) {
                    float4 a = *(const float4*)(wbuf + pxl * 40 + k * 4);
                    float4 b = *(const float4*)(wbuf + (pxl + 1) * 40 + k * 4);
                    wk[k][0] = pack2(a.x, b.x);
                    wk[k][1] = pack2(a.y, b.y);
                    wk[k][2] = pack2(a.z, b.z);
                    wk[k][3] = pack2(a.w, b.w);
                }
            }

            const int h    = hr4 + 2 * p + row;
            const int rloc = 2 * p + row;      // buf row for dy=0 (global h-1)
            float* opb = out + ((size_t)n * Cc * HW) * 4 + (2 * h) * 128 + 4 * lane;

            #pragma unroll 1
            for (int c = 0; c < 32; c++) {
                if (c == 31) cp_wait0(); else cp_wait1();
                BARR();

                if (c < 30) {
                    const float* gch = xb + (size_t)((c + 2) * 8) * HW;
                    u32 sb2 = sb + S_HALO + ((c + 2) % 3) * CHUNKB;
                    #pragma unroll
                    for (int i = 0; i < 4; i++)
                        if (act[i]) cp_async16(sb2 + smOff[i], pred[i] ? gch + gOff[i] : xb,
                                               pred[i] ? 16u : 0u);
                    cp_commit();
                }

                const float* buf = (const float*)(smem + S_HALO + (c % 3) * CHUNKB);
                #pragma unroll
                for (int e = 0; e < 2; e++) {
                    const int chl = cq * 2 + e;
                    const int chg = c * 8 + chl;
                    const float* basep = buf + (chl * 6 + rloc) * 72 + 2 * lane + 2;
                    u64 a0 = 0ULL, a1 = 0ULL, a2 = 0ULL, a3 = 0ULL;
                    #pragma unroll
                    for (int dy = 0; dy < 3; dy++) {
                        const float* rp = basep + dy * 72;
                        u64 t0 = *(const u64*)(rp);
                        u64 t1 = *(const u64*)(rp + 2);
                        u64 t2v = *(const u64*)(rp + 4);
                        float2 f0 = unpack2(t0);
                        float2 f1 = unpack2(t1);
                        float2 f2 = unpack2(t2v);
                        u64 xp0 = pack2(f0.y, f1.x);
                        u64 xp1 = t1;
                        u64 xp2 = pack2(f1.y, f2.x);
                        int k = dy * 3;
                        fma2(a0, xp0, wk[k][0]); fma2(a1, xp0, wk[k][1]);
                        fma2(a2, xp0, wk[k][2]); fma2(a3, xp0, wk[k][3]);
                        fma2(a0, xp1, wk[k + 1][0]); fma2(a1, xp1, wk[k + 1][1]);
                        fma2(a2, xp1, wk[k + 1][2]); fma2(a3, xp1, wk[k + 1][3]);
                        fma2(a0, xp2, wk[k + 2][0]); fma2(a1, xp2, wk[k + 2][1]);
                        fma2(a2, xp2, wk[k + 2][2]); fma2(a3, xp2, wk[k + 2][3]);
                    }
                    float2 r0 = unpack2(a0), r1 = unpack2(a1);
                    float2 r2 = unpack2(a2), r3 = unpack2(a3);
                    float* op = opb + (size_t)chg * (HW * 4);
                    stcs4(op,       make_float4(r0.x, r1.x, r0.y, r1.y));
                    stcs4(op + 128, make_float4(r2.x, r3.x, r2.y, r3.y));
                }
            }
        }
    }
}

extern "C" void kernel_launch(void* const* d_in, const int* in_sizes, int n_in,
                              void* d_out, int out_size)
{
    const float* x     = (const float*)d_in[0];
    const float* w0    = (const float*)d_in[1];
    const float* b0    = (const float*)d_in[2];
    const float* bn0_g = (const float*)d_in[3];
    const float* bn0_b = (const float*)d_in[4];
    const float* bn0_m = (const float*)d_in[5];
    const float* bn0_v = (const float*)d_in[6];
    const float* w1    = (const float*)d_in[7];
    const float* b1    = (const float*)d_in[8];
    const float* bn1_g = (const float*)d_in[9];
    const float* bn1_b = (const float*)d_in[10];
    const float* bn1_m = (const float*)d_in[11];
    const float* bn1_v = (const float*)d_in[12];
    float* out = (float*)d_out;

    cudaFuncSetAttribute(k_fused, cudaFuncAttributeMaxDynamicSharedMemorySize, SMEMF);

    dim3 g(16, Nn);    // 16 four-row tiles x 8 batches = 128 CTAs
    k_fused<<<g, 512, SMEMF>>>(x, w0, b0, bn0_g, bn0_b, bn0_m, bn0_v,
                               w1, b1, bn1_g, bn1_b, bn1_m, bn1_v, out);
}

// round 16
// speedup vs baseline: 1.2692x; 1.2692x over previous
#include <cuda_runtime.h>
#include <cstdint>

#define EPS 1e-5f
#define Nn 8
#define Cc 256
#define Hh 64
#define Ww 64
#define HW 4096
#define OC 64
#define Pp 36

typedef unsigned long long u64;
typedef unsigned int u32;
typedef unsigned short u16;

// softmax weights scratch, layout [n][h][36][w] (w contiguous)
__device__ float g_wts[(size_t)Nn * HW * Pp];

__device__ __forceinline__ u64 pack2(float x, float y) {
    u64 r; asm("mov.b64 %0, {%1,%2};" : "=l"(r) : "f"(x), "f"(y)); return r;
}
__device__ __forceinline__ void fma2(u64 &d, u64 a, u64 b) {
    asm("fma.rn.f32x2 %0, %1, %2, %0;" : "+l"(d) : "l"(a), "l"(b));
}
__device__ __forceinline__ float2 unpack2(u64 v) {
    float2 r; asm("mov.b64 {%0,%1}, %2;" : "=f"(r.x), "=f"(r.y) : "l"(v)); return r;
}
__device__ __forceinline__ u32 smem_u32(const void* p) {
    u32 a;
    asm("{ .reg .u64 t; cvta.to.shared.u64 t, %1; cvt.u32.u64 %0, t; }" : "=r"(a) : "l"(p));
    return a;
}
__device__ __forceinline__ void ldsm4(u32& r0, u32& r1, u32& r2, u32& r3, u32 addr) {
    asm volatile("ldmatrix.sync.aligned.m8n8.x4.shared.b16 {%0,%1,%2,%3}, [%4];"
                 : "=r"(r0), "=r"(r1), "=r"(r2), "=r"(r3) : "r"(addr));
}
__device__ __forceinline__ void ldsm4t(u32& r0, u32& r1, u32& r2, u32& r3, u32 addr) {
    asm volatile("ldmatrix.sync.aligned.m8n8.x4.trans.shared.b16 {%0,%1,%2,%3}, [%4];"
                 : "=r"(r0), "=r"(r1), "=r"(r2), "=r"(r3) : "r"(addr));
}
__device__ __forceinline__ void mma16816(float* c, u32 a0, u32 a1, u32 a2, u32 a3,
                                          u32 b0, u32 b1) {
    asm volatile("mma.sync.aligned.m16n8k16.row.col.f32.bf16.bf16.f32 "
                 "{%0,%1,%2,%3}, {%4,%5,%6,%7}, {%8,%9}, {%0,%1,%2,%3};"
                 : "+f"(c[0]), "+f"(c[1]), "+f"(c[2]), "+f"(c[3])
                 : "r"(a0), "r"(a1), "r"(a2), "r"(a3), "r"(b0), "r"(b1));
}
__device__ __forceinline__ void split2(float vx, float vy, u32& hi, u32& lo) {
    u32 h; asm("cvt.rn.bf16x2.f32 %0, %1, %2;" : "=r"(h) : "f"(vy), "f"(vx));
    float hx = __uint_as_float(h << 16);
    float hy = __uint_as_float(h & 0xffff0000u);
    u32 l; asm("cvt.rn.bf16x2.f32 %0, %1, %2;" : "=r"(l) : "f"(vy - hy), "f"(vx - hx));
    hi = h; lo = l;
}
__device__ __forceinline__ u16 bf16hi(float v) {
    u16 h; asm("cvt.rn.bf16.f32 %0, %1;" : "=h"(h) : "f"(v)); return h;
}

// ---------------------------------------------------------------------------
// Kernel 1: weights. GEMM0 + encoder on mma.sync (R14 body, unchanged).
// ---------------------------------------------------------------------------
#define S_AHI   0
#define S_ALO   34816
#define S_WHI   69632
#define S_WLO   87040
#define S_CST   104448
#define SMEM1   105280

#define S2_AHI  0
#define S2_ALO  17408
#define S2_WHI  34816
#define S2_WLO  47872
#define S2_L    60928
#define S2_WTS  0

extern "C" __global__ void __launch_bounds__(256, 2)
k_weights(const float* __restrict__ x,
          const float* __restrict__ w0, const float* __restrict__ b0,
          const float* __restrict__ bn0_g, const float* __restrict__ bn0_b,
          const float* __restrict__ bn0_m, const float* __restrict__ bn0_v,
          const float* __restrict__ w1, const float* __restrict__ b1,
          const float* __restrict__ bn1_g, const float* __restrict__ bn1_b,
          const float* __restrict__ bn1_m, const float* __restrict__ bn1_v)
{
    extern __shared__ char smem[];
    const u32 sb = smem_u32(smem);
    float* cA0 = (float*)(smem + S_CST);
    float* cB0 = cA0 + 64;
    float* cA1 = cB0 + 64;
    float* cB1 = cA1 + 40;
    float* wts_s = (float*)(smem + S2_WTS);
    float* L     = (float*)(smem + S2_L);

    const int t = threadIdx.x;
    const int warp = t >> 5, lane = t & 31;
    const int n = blockIdx.y, p0 = blockIdx.x * 128;

    if (t < 64) {
        float A = bn0_g[t] * rsqrtf(bn0_v[t] + EPS);
        cA0[t] = A;
        cB0[t] = (b0[t] - bn0_m[t]) * A + bn0_b[t];
    } else if (t < 64 + 40) {
        int i = t - 64;
        if (i < Pp) {
            float A = bn1_g[i] * rsqrtf(bn1_v[i] + EPS);
            cA1[i] = A;
            cB1[i] = (b1[i] - bn1_m[i]) * A + bn1_b[i];
        } else { cA1[i] = 0.f; cB1[i] = 0.f; }
    }

    float2 w1r[5];
    #pragma unroll
    for (int r = 0; r < 5; r++) {
        int i = t + 256 * r;
        w1r[r] = *(const float2*)(w1 + (i >> 5) * OC + (i & 31) * 2);
    }

    const int mat = lane >> 3, mr = lane & 7;
    const int m0 = warp * 16;
    const int g  = lane >> 2, tq = lane & 3;
    const u32 a_off = (u32)((((mat >> 1) * 8) + mr) * 272 + (m0 + (mat & 1) * 8) * 2);
    const u32 b_off = (u32)((((mat >> 1) * 8) + mr) * 272 + (mat & 1) * 16);

    float acc[8][4];
    #pragma unroll
    for (int i = 0; i < 8; i++)
        #pragma unroll
        for (int j = 0; j < 4; j++) acc[i][j] = 0.f;

    #pragma unroll 1
    for (int h = 0; h < 2; h++) {
        __syncthreads();
        {
            const float4* xr = (const float4*)(x + ((size_t)n * Cc + h * 128 + warp * 16) * HW + p0);
            char* ahb = smem + S_AHI + (warp * 16) * 272 + lane * 8;
            char* alb = smem + S_ALO + (warp * 16) * 272 + lane * 8;
            #pragma unroll 8
            for (int rr = 0; rr < 16; rr++) {
                float4 v = xr[lane];
                u32 h0, l0, h1, l1;
                split2(v.x, v.y, h0, l0);
                split2(v.z, v.w, h1, l1);
                *(uint2*)(ahb) = make_uint2(h0, h1);
                *(uint2*)(alb) = make_uint2(l0, l1);
                xr += HW / 4;
                ahb += 272; alb += 272;
            }
        }
        {
            #pragma unroll 8
            for (int it = 0; it < 8; it++) {
                int oc = it * 8 + warp;
                float4 v = *(const float4*)(w0 + (size_t)oc * Cc + h * 128 + lane * 4);
                u32 h0, l0, h1, l1;
                split2(v.x, v.y, h0, l0);
                split2(v.z, v.w, h1, l1);
                *(uint2*)(smem + S_WHI + oc * 272 + lane * 8) = make_uint2(h0, h1);
                *(uint2*)(smem + S_WLO + oc * 272 + lane * 8) = make_uint2(l0, l1);
            }
        }
        __syncthreads();

        #pragma unroll
        for (int ks = 0; ks < 8; ks++) {
            u32 ah0, ah1, ah2, ah3, al0, al1, al2, al3;
            ldsm4t(ah0, ah1, ah2, ah3, sb + S_AHI + ks * 4352 + a_off);
            ldsm4t(al0, al1, al2, al3, sb + S_ALO + ks * 4352 + a_off);
            #pragma unroll
            for (int j = 0; j < 4; j++) {
                u32 bh0, bh1, bh2, bh3, bl0, bl1, bl2, bl3;
                ldsm4(bh0, bh1, bh2, bh3, sb + S_WHI + j * 16 * 272 + ks * 32 + b_off);
                ldsm4(bl0, bl1, bl2, bl3, sb + S_WLO + j * 16 * 272 + ks * 32 + b_off);
                mma16816(acc[2 * j],     ah0, ah1, ah2, ah3, bh0, bh1);
                mma16816(acc[2 * j],     al0, al1, al2, al3, bh0, bh1);
                mma16816(acc[2 * j],     ah0, ah1, ah2, ah3, bl0, bl1);
                mma16816(acc[2 * j + 1], ah0, ah1, ah2, ah3, bh2, bh3);
                mma16816(acc[2 * j + 1], al0, al1, al2, al3, bh2, bh3);
                mma16816(acc[2 * j + 1], ah0, ah1, ah2, ah3, bl2, bl3);
            }
        }
    }
    __syncthreads();

    {
        const int pxa = m0 + g, pxb = m0 + g + 8;
        #pragma unroll
        for (int j = 0; j < 8; j++) {
            int oc0 = 8 * j + 2 * tq, oc1 = oc0 + 1;
            float Aa = cA0[oc0], Ba = cB0[oc0];
            float Ab = cA0[oc1], Bb = cB0[oc1];
            float v00 = fmaxf(fmaf(acc[j][0], Aa, Ba), 0.f);
            float v01 = fmaxf(fmaf(acc[j][1], Ab, Bb), 0.f);
            float v10 = fmaxf(fmaf(acc[j][2], Aa, Ba), 0.f);
            float v11 = fmaxf(fmaf(acc[j][3], Ab, Bb), 0.f);
            #pragma unroll
            for (int q = 0; q < 4; q++) {
                float v  = (q == 0) ? v00 : (q == 1) ? v01 : (q == 2) ? v10 : v11;
                int oc   = (q & 1) ? oc1 : oc0;
                int px   = (q & 2) ? pxb : pxa;
                u16 hi = bf16hi(v);
                float hf = __uint_as_float(((u32)hi) << 16);
                u16 lo = bf16hi(v - hf);
                *(u16*)(smem + S2_AHI + oc * 272 + px * 2) = hi;
                *(u16*)(smem + S2_ALO + oc * 272 + px * 2) = lo;
            }
        }
    }
    #pragma unroll
    for (int r = 0; r < 5; r++) {
        int i = t + 256 * r;
        int p = i >> 5, oq = i & 31;
        u32 hi, lo;
        split2(w1r[r].x, w1r[r].y, hi, lo);
        *(u32*)(smem + S2_WHI + p * 272 + oq * 4) = hi;
        *(u32*)(smem + S2_WLO + p * 272 + oq * 4) = lo;
    }
    for (int i = t; i < 8 * 68; i += 256) {
        int row = 40 + i / 68, col = i % 68;
        *(u32*)(smem + S2_WHI + row * 272 + col * 4) = 0;
        *(u32*)(smem + S2_WLO + row * 272 + col * 4) = 0;
    }
    __syncthreads();

    float d1[5][4];
    #pragma unroll
    for (int i = 0; i < 5; i++)
        #pragma unroll
        for (int j = 0; j < 4; j++) d1[i][j] = 0.f;

    #pragma unroll
    for (int ks = 0; ks < 4; ks++) {
        u32 ah0, ah1, ah2, ah3, al0, al1, al2, al3;
        ldsm4t(ah0, ah1, ah2, ah3, sb + S2_AHI + ks * 4352 + a_off);
        ldsm4t(al0, al1, al2, al3, sb + S2_ALO + ks * 4352 + a_off);
        #pragma unroll
        for (int rb = 0; rb < 3; rb++) {
            u32 bh0, bh1, bh2, bh3, bl0, bl1, bl2, bl3;
            ldsm4(bh0, bh1, bh2, bh3, sb + S2_WHI + rb * 4352 + ks * 32 + b_off);
            ldsm4(bl0, bl1, bl2, bl3, sb + S2_WLO + rb * 4352 + ks * 32 + b_off);
            int nt = 2 * rb;
            mma16816(d1[nt], ah0, ah1, ah2, ah3, bh0, bh1);
            mma16816(d1[nt], al0, al1, al2, al3, bh0, bh1);
            mma16816(d1[nt], ah0, ah1, ah2, ah3, bl0, bl1);
            if (rb < 2) {
                mma16816(d1[nt + 1], ah0, ah1, ah2, ah3, bh2, bh3);
                mma16816(d1[nt + 1], al0, al1, al2, al3, bh2, bh3);
                mma16816(d1[nt + 1], ah0, ah1, ah2, ah3, bl2, bl3);
            }
        }
    }
    #pragma unroll
    for (int nt = 0; nt < 5; nt++) {
        int pc0 = 8 * nt + 2 * tq, pc1 = pc0 + 1;
        float Aa = cA1[pc0], Ba = cB1[pc0];
        float Ab = cA1[pc1], Bb = cB1[pc1];
        L[(m0 + g) * 49 + pc0]     = fmaxf(fmaf(d1[nt][0], Aa, Ba), 0.f);
        L[(m0 + g) * 49 + pc1]     = fmaxf(fmaf(d1[nt][1], Ab, Bb), 0.f);
        L[(m0 + g + 8) * 49 + pc0] = fmaxf(fmaf(d1[nt][2], Aa, Ba), 0.f);
        L[(m0 + g + 8) * 49 + pc1] = fmaxf(fmaf(d1[nt][3], Ab, Bb), 0.f);
    }
    __syncthreads();

    {
        const int px = t & 127;
        const int hh = t >> 7;
        const float* Lp = L + px * 49;
        #pragma unroll
        for (int uu = 0; uu < 2; uu++) {
            int u = hh + 2 * uu;
            float e[9], mx = -1e30f;
            #pragma unroll
            for (int k = 0; k < 9; k++) { e[k] = Lp[k * 4 + u]; mx = fmaxf(mx, e[k]); }
            float s = 0.f;
            #pragma unroll
            for (int k = 0; k < 9; k++) { float q = __expf(e[k] - mx); e[k] = q; s += q; }
            float inv = 1.f / s;
            #pragma unroll
            for (int k = 0; k < 9; k++) wts_s[px * 37 + k * 4 + u] = e[k] * inv;
        }
    }
    __syncthreads();

    {
        const int hrow = p0 >> 6;
        float* gb = g_wts + (size_t)(n * Hh + hrow) * (36 * 64);
        for (int i = t; i < 2 * 36 * 64; i += 256) {
            int w = i & 63;
            int c = (i >> 6) % 36;
            int r = i / (36 * 64);
            gb[(size_t)(r * 36 + c) * 64 + w] = wts_s[(r * 64 + w) * 37 + c];
        }
    }
}

// ---------------------------------------------------------------------------
// Kernel 2: reassembly, 2 px/thread STG.128 (R14 engine), re-tiled to
// 128-thread blocks x 512 CTAs so all 148 SMs are used in one wave.
// Block: 4 h-rows x 32 pixel pairs, 64 channels (c-split 4).
// Dynamic smem: 3 x [8ch][6rows][72f] = 41472 B -> 4 CTAs/SM.
// ---------------------------------------------------------------------------
__device__ __forceinline__ void cp_async16(u32 dst, const void* src, u32 srcsz) {
    asm volatile("cp.async.cg.shared.global [%0], [%1], 16, %2;"
                 :: "r"(dst), "l"(src), "r"(srcsz));
}
__device__ __forceinline__ void cp_commit() { asm volatile("cp.async.commit_group;"); }
__device__ __forceinline__ void cp_wait1() { asm volatile("cp.async.wait_group 1;" ::: "memory"); }
__device__ __forceinline__ void cp_wait0() { asm volatile("cp.async.wait_group 0;" ::: "memory"); }
__device__ __forceinline__ void stcs4(float* p, float4 v) {
    asm volatile("st.global.cs.v4.f32 [%0], {%1,%2,%3,%4};"
                 :: "l"(p), "f"(v.x), "f"(v.y), "f"(v.z), "f"(v.w));
}

#define ROWF2    72
#define CHUNK2_B (8 * 6 * ROWF2 * 4)     // 13824
#define SMEM2    (3 * CHUNK2_B)          // 41472

extern "C" __global__ void __launch_bounds__(128, 4)
k_reassemble(const float* __restrict__ x, float* __restrict__ out)
{
    extern __shared__ float xsf[];
    const u32 s_base = smem_u32(xsf);

    const int tid = threadIdx.x;
    const int tx  = tid & 31;           // pixel pair index: px = 2tx, 2tx+1
    const int ty  = tid >> 5;           // h row within tile (0..3)
    const int h0  = blockIdx.x * 4;
    const int n   = blockIdx.y >> 2;
    const int c0  = (blockIdx.y & 3) * 64;
    const int h   = h0 + ty;

    const float* xb = x + (size_t)n * Cc * HW;

    // ---- hoisted loader: 864 vec4 per chunk = 8ch x 6rows x 18vec; 7/thread ----
    u32  smOff[7];
    int  gOff[7];
    bool pred[7], act[7];
    #pragma unroll
    for (int i = 0; i < 7; i++) {
        int idx = i * 128 + tid;
        act[i] = idx < 864;
        int ch  = idx / 108;
        int rem = idx - ch * 108;
        int row = rem / 18, j = rem - row * 18;
        bool rok = ((unsigned)(h0 - 1 + row) < (unsigned)Hh);
        bool cok = (j >= 1) && (j <= 16);
        pred[i]  = act[i] && rok && cok;
        smOff[i] = (u32)(((ch * 6 + row) * ROWF2 + 4 * j) * 4);
        gOff[i]  = ch * HW + (h0 - 1 + row) * Ww + (4 * j - 4);
    }

    // prefetch chunks 0,1
    #pragma unroll
    for (int c = 0; c < 2; c++) {
        const float* gch = xb + (size_t)(c0 + c * 8) * HW;
        u32 sb2 = s_base + c * CHUNK2_B;
        #pragma unroll
        for (int i = 0; i < 7; i++)
            if (act[i]) cp_async16(sb2 + smOff[i], pred[i] ? gch + gOff[i] : xb,
                                   pred[i] ? 16u : 0u);
        cp_commit();
    }

    // ---- weights: cross-pixel packed pairs ----
    u64 wk[9][4];
    {
        const float2* wb2 = (const float2*)(g_wts + (size_t)(n * Hh + h) * (36 * 64));
        #pragma unroll
        for (int k = 0; k < 9; k++)
            #pragma unroll
            for (int u = 0; u < 4; u++) {
                float2 v = __ldg(wb2 + (k * 4 + u) * 32 + tx);
                wk[k][u] = pack2(v.x, v.y);
            }
    }

    float* opb = out + ((size_t)(n * Cc + c0) * HW) * 4 + (2 * h) * 128 + 4 * tx;

    #pragma unroll 1
    for (int ch8 = 0; ch8 < 8; ch8++) {
        if (ch8 == 7) cp_wait0(); else cp_wait1();
        __syncthreads();

        if (ch8 < 6) {
            const float* gch = xb + (size_t)(c0 + (ch8 + 2) * 8) * HW;
            u32 sb2 = s_base + ((ch8 + 2) % 3) * CHUNK2_B;
            #pragma unroll
            for (int i = 0; i < 7; i++)
                if (act[i]) cp_async16(sb2 + smOff[i], pred[i] ? gch + gOff[i] : xb,
                                       pred[i] ? 16u : 0u);
            cp_commit();
        }

        const float* bufp = xsf + ((ch8 % 3) * CHUNK2_B) / 4 + ty * ROWF2 + 2 * tx + 2;
        float* op = opb + (size_t)ch8 * 8 * (HW * 4);
        #pragma unroll
        for (int cl = 0; cl < 8; cl++) {
            const float* rowp = bufp + cl * 6 * ROWF2;
            u64 a0 = 0ULL, a1 = 0ULL, a2 = 0ULL, a3 = 0ULL;
            #pragma unroll
            for (int dy = 0; dy < 3; dy++) {
                const float* rp = rowp + dy * ROWF2;
                u64 t0 = *(const u64*)(rp);        // cols 2tx+2, 2tx+3
                u64 t1 = *(const u64*)(rp + 2);    // cols 2tx+4, 2tx+5
                u64 t2 = *(const u64*)(rp + 4);    // cols 2tx+6, 2tx+7
                float2 f0 = unpack2(t0);
                float2 f1 = unpack2(t1);
                float2 f2 = unpack2(t2);
                u64 xp0 = pack2(f0.y, f1.x);
                u64 xp1 = t1;
                u64 xp2 = pack2(f1.y, f2.x);
                int k = dy * 3;
                fma2(a0, xp0, wk[k][0]); fma2(a1, xp0, wk[k][1]);
                fma2(a2, xp0, wk[k][2]); fma2(a3, xp0, wk[k][3]);
                fma2(a0, xp1, wk[k + 1][0]); fma2(a1, xp1, wk[k + 1][1]);
                fma2(a2, xp1, wk[k + 1][2]); fma2(a3, xp1, wk[k + 1][3]);
                fma2(a0, xp2, wk[k + 2][0]); fma2(a1, xp2, wk[k + 2][1]);
                fma2(a2, xp2, wk[k + 2][2]); fma2(a3, xp2, wk[k + 2][3]);
            }
            float2 r0 = unpack2(a0), r1 = unpack2(a1);
            float2 r2 = unpack2(a2), r3 = unpack2(a3);
            stcs4(op,       make_float4(r0.x, r1.x, r0.y, r1.y));   // row 2h
            stcs4(op + 128, make_float4(r2.x, r3.x, r2.y, r3.y));   // row 2h+1
            op += HW * 4;
        }
    }
}

extern "C" void kernel_launch(void* const* d_in, const int* in_sizes, int n_in,
                              void* d_out, int out_size)
{
    const float* x     = (const float*)d_in[0];
    const float* w0    = (const float*)d_in[1];
    const float* b0    = (const float*)d_in[2];
    const float* bn0_g = (const float*)d_in[3];
    const float* bn0_b = (const float*)d_in[4];
    const float* bn0_m = (const float*)d_in[5];
    const float* bn0_v = (const float*)d_in[6];
    const float* w1    = (const float*)d_in[7];
    const float* b1    = (const float*)d_in[8];
    const float* bn1_g = (const float*)d_in[9];
    const float* bn1_b = (const float*)d_in[10];
    const float* bn1_m = (const float*)d_in[11];
    const float* bn1_v = (const float*)d_in[12];
    float* out = (float*)d_out;

    cudaFuncSetAttribute(k_weights, cudaFuncAttributeMaxDynamicSharedMemorySize, SMEM1);
    cudaFuncSetAttribute(k_reassemble, cudaFuncAttributeMaxDynamicSharedMemorySize, SMEM2);

    dim3 g1(32, Nn);
    k_weights<<<g1, 256, SMEM1>>>(x, w0, b0, bn0_g, bn0_b, bn0_m, bn0_v,
                                  w1, b1, bn1_g, bn1_b, bn1_m, bn1_v);

    dim3 g2(16, Nn * 4);       // 512 CTAs, 128 threads
    k_reassemble<<<g2, 128, SMEM2>>>(x, out);
}